// round 13
// baseline (speedup 1.0000x reference)
#include <cuda_runtime.h>
#include <cuda_fp16.h>
#include <math.h>
#include <stdint.h>

#define T_STEPS 50
#define BATCH   1024
#define NPD     512
#define NHD     512
#define NGD     4096
#define RING    16
#define HXB     8

#define STAGE_B   20480u                  // 256 rows x 80 bytes
#define NSTAGE    4
#define SMEM_DYN  (NSTAGE * 20480)        // 81920 B
#define RP        80                      // row pitch bytes (40 halves)

// ---------------- device scratch (no cudaMalloc allowed) ----------------
__device__ __half d_hxh[HXB][BATCH * NHD];
__device__ float  d_cx[BATCH * NHD];
__device__ __half d_gbufh[RING][(size_t)BATCH * NGD];     // 128 MB ring
__device__ __half d_p0h[BATCH * NPD];
__device__ __half d_e1h[NHD * NPD];
__device__ __half d_e2h[NHD * NPD];
__device__ __half d_whhh[4 * NHD * NHD];                  // permuted [h*4+g][k]
__device__ __half d_gwh[(size_t)NGD * NHD];
__device__ __half d_dech[(size_t)NPD * NGD];
__device__ float4 d_bsum4[NHD];
__device__ float4 d_wihp[2 * NHD];
__device__ float  d_encb1[NHD];
__device__ float  d_encb2[NHD];
__device__ float  d_decb[NPD];

// dataflow counters (zeroed per replay)
__device__ int d_scnt[64][8];             // hx block ready (16/launch + 32 enc)
__device__ int d_gcnt[T_STEPS][8];        // g m-block ready: 32 n-tiles each

__device__ __forceinline__ uint32_t sm_u32(const void* p) {
    return (uint32_t)__cvta_generic_to_shared(p);
}

#define CP_ASYNC16(dst, src) \
    asm volatile("cp.async.cg.shared.global [%0], [%1], 16;\n" :: "r"(dst), "l"(src))
#define CP_COMMIT() asm volatile("cp.async.commit_group;\n" ::: "memory")
#define CP_WAIT0()  asm volatile("cp.async.wait_group 0;\n" ::: "memory")
#define CP_WAIT1()  asm volatile("cp.async.wait_group 1;\n" ::: "memory")
#define CP_WAIT2()  asm volatile("cp.async.wait_group 2;\n" ::: "memory")

#define LDSM_X4(r0, r1, r2, r3, addr) \
    asm volatile("ldmatrix.sync.aligned.m8n8.x4.shared.b16 {%0,%1,%2,%3}, [%4];" \
                 : "=r"(r0), "=r"(r1), "=r"(r2), "=r"(r3) : "r"(addr))

__device__ __forceinline__ void mma_f16(float* c, uint32_t a0, uint32_t a1,
                                        uint32_t a2, uint32_t a3,
                                        uint32_t b0, uint32_t b1)
{
    asm volatile(
        "mma.sync.aligned.m16n8k16.row.col.f32.f16.f16.f32 "
        "{%0,%1,%2,%3}, {%4,%5,%6,%7}, {%8,%9}, {%0,%1,%2,%3};"
        : "+f"(c[0]), "+f"(c[1]), "+f"(c[2]), "+f"(c[3])
        : "r"(a0), "r"(a1), "r"(a2), "r"(a3), "r"(b0), "r"(b1));
}

__device__ __forceinline__ void spin_ge(volatile int* p, int target) {
    while (*p < target) __nanosleep(64);
}

// roles
#define R_GATES 0
#define R_G     1
#define R_DEC   2
#define R_ENCH  3
#define R_ENCC  4

// ---------------------------------------------------------------------------
// Mega kernel, one CTA per fp16 GEMM tile. Step launch L in [0, 52):
//   bx [0,128)   : gates(t=L)    128x128x512, fused LSTM cell  [valid L<50]
//   bx [128,160) : decode(td=L-2) 128x128x4096, single write   [valid td<50]
//   bx [160,416) : g(t=L-1)      128x128x512, relu -> ring     [valid 1<=L<=50]
// L=-1: encoder (64 CTAs). PDL trigger at entry; true deps via counters.
// 4-stage cp.async pipeline in dynamic smem. Decode early = longest-job-first.
// ---------------------------------------------------------------------------
__global__ void __launch_bounds__(256, 2)
mega(int L, float* __restrict__ out, const float* __restrict__ vp)
{
    asm volatile("griddepcontrol.launch_dependents;" ::: "memory");

    extern __shared__ __align__(16) char smraw[];
    const uint32_t smb = sm_u32(smraw);

    const int tid  = threadIdx.x;
    const int lane = tid & 31;
    const int wid  = tid >> 5;
    const int lg   = lane >> 2;
    const int l4   = lane & 3;
    const int wm   = (wid >> 2) * 64;
    const int wn   = (wid & 3) * 32;
    const int bx   = blockIdx.x;

    int role, m0, n0, td = 0, lda, KT = 16;
    const __half *Ab, *Wb;

    if (L < 0) {
        role = (bx < 32) ? R_ENCH : R_ENCC;
        const int s = bx & 31;
        m0 = (s >> 2) << 7; n0 = (s & 3) << 7;
        Ab = d_p0h + (size_t)m0 * NPD;
        Wb = ((role == R_ENCH) ? d_e1h : d_e2h) + (size_t)n0 * NPD;
        lda = 512;
    } else if (bx < 128) {
        if (L >= T_STEPS) return;
        role = R_GATES;
        n0 = (bx & 15) << 7; m0 = (bx >> 4) << 7;
        Ab = &d_hxh[L % HXB][0] + (size_t)m0 * NHD;
        Wb = d_whhh + (size_t)n0 * NHD;
        lda = 512;
    } else if (bx < 160) {
        td = L - 2;
        if (td < 0 || td >= T_STEPS) return;
        role = R_DEC;
        const int s = bx - 128;           // 0..31
        m0 = (s >> 2) << 7; n0 = (s & 3) << 7;
        Ab = &d_gbufh[td & (RING - 1)][0] + (size_t)m0 * NGD;
        Wb = d_dech + (size_t)n0 * NGD;
        lda = NGD;
        KT = 128;
    } else {
        if (L < 1 || L > T_STEPS) return;
        role = R_G;
        const int s = bx - 160;
        n0 = (s & 31) << 7; m0 = (s >> 5) << 7;
        Ab = &d_hxh[L % HXB][0] + (size_t)m0 * NHD;
        Wb = d_gwh + (size_t)n0 * NHD;
        lda = 512;
    }

    // ---- wait for true data dependencies (producers in earlier launches) ----
    if (tid == 0) {
        if (role == R_GATES || role == R_G)
            spin_ge(&d_scnt[L][m0 >> 7], (L == 0) ? 32 : 16);
        else if (role == R_DEC)
            spin_ge(&d_gcnt[td][m0 >> 7], 32);
        __threadfence();
    }
    __syncthreads();

    float acc[4][4][4];
#pragma unroll
    for (int i = 0; i < 4; i++)
#pragma unroll
        for (int j = 0; j < 4; j++)
#pragma unroll
            for (int e = 0; e < 4; e++) acc[i][j][e] = 0.f;

    auto load_stage = [&](int kt, int stage) {
        const uint32_t sb = smb + stage * STAGE_B;
#pragma unroll
        for (int it = 0; it < 4; it++) {
            const int i    = tid + it * 256;
            const int row  = i >> 2;
            const int quad = i & 3;
            const __half* src =
                ((row < 128) ? Ab + (size_t)row * lda
                             : Wb + (size_t)(row - 128) * lda)
                + (kt << 5) + (quad << 3);
            CP_ASYNC16(sb + row * RP + (quad << 4), src);
        }
        CP_COMMIT();
    };

    // ldmatrix lane base addresses (stage 0; add stage/ks offsets per use)
    uint32_t aAdr[4], bAdr[2];
#pragma unroll
    for (int ti = 0; ti < 4; ti++)
        aAdr[ti] = smb + (wm + ti * 16 + (lane & 15)) * RP + ((lane >> 4) << 4);
#pragma unroll
    for (int p = 0; p < 2; p++)
        bAdr[p] = smb + (128 + wn + p * 16 + ((lane >> 4) << 3) + (lane & 7)) * RP
                + (((lane >> 3) & 1) << 4);

    load_stage(0, 0);
    load_stage(1, 1);
    load_stage(2, 2);
    int issued = 3;

#pragma unroll 1
    for (int kt = 0; kt < KT; kt++) {
        const int outg = issued - kt - 1;     // outstanding groups after kt's done
        if (outg >= 2)      { CP_WAIT2(); }
        else if (outg == 1) { CP_WAIT1(); }
        else                { CP_WAIT0(); }
        __syncthreads();
        if (issued < KT) { load_stage(issued, issued & 3); issued++; }

        const uint32_t so = (kt & 3) * STAGE_B;
#pragma unroll
        for (int ks = 0; ks < 2; ks++) {
            const uint32_t ko = so + ks * 32;
            uint32_t af[4][4], bf[2][4];
#pragma unroll
            for (int p = 0; p < 2; p++)
                LDSM_X4(bf[p][0], bf[p][1], bf[p][2], bf[p][3], bAdr[p] + ko);
#pragma unroll
            for (int ti = 0; ti < 4; ti++)
                LDSM_X4(af[ti][0], af[ti][1], af[ti][2], af[ti][3], aAdr[ti] + ko);
#pragma unroll
            for (int ti = 0; ti < 4; ti++)
#pragma unroll
                for (int tj = 0; tj < 4; tj++)
                    mma_f16(acc[ti][tj],
                            af[ti][0], af[ti][1], af[ti][2], af[ti][3],
                            bf[tj >> 1][(tj & 1) * 2],
                            bf[tj >> 1][(tj & 1) * 2 + 1]);
        }
    }

    // ---------------- epilogues ----------------
    if (role == R_DEC) {
        float* ob = out + (size_t)td * BATCH * NPD;
#pragma unroll
        for (int ti = 0; ti < 4; ti++) {
            const int r0 = m0 + wm + ti * 16 + lg;
#pragma unroll
            for (int tj = 0; tj < 4; tj++) {
                const int col = n0 + wn + tj * 8 + 2 * l4;
                float* c = acc[ti][tj];
                const float b0 = d_decb[col], b1 = d_decb[col + 1];
                *(float2*)(ob + (size_t)r0 * NPD + col) =
                    make_float2(c[0] + b0, c[1] + b1);
                *(float2*)(ob + (size_t)(r0 + 8) * NPD + col) =
                    make_float2(c[2] + b0, c[3] + b1);
            }
        }
        return;
    }

    if (role == R_GATES) {
        float*  cxp = d_cx;
        __half* hxp = &d_hxh[(L + 1) % HXB][0];
        const int hbase = (n0 >> 2) + (wn >> 2);
#pragma unroll
        for (int ti = 0; ti < 4; ti++) {
            const int myrow = m0 + wm + ti * 16 + lg + ((l4 & 1) << 3);
            const float2 vv = *(const float2*)(vp + ((size_t)L * BATCH + myrow) * 2);
#pragma unroll
            for (int tj = 0; tj < 4; tj++) {
                const int h = hbase + tj * 2 + (l4 >> 1);
                float* c = acc[ti][tj];
                float2 send = (l4 & 1) ? make_float2(c[0], c[1])
                                       : make_float2(c[2], c[3]);
                float2 recv;
                recv.x = __shfl_xor_sync(0xffffffffu, send.x, 1);
                recv.y = __shfl_xor_sync(0xffffffffu, send.y, 1);
                float g0, g1, g2, g3;
                if (!(l4 & 1)) { g0 = c[0]; g1 = c[1]; g2 = recv.x; g3 = recv.y; }
                else           { g0 = recv.x; g1 = recv.y; g2 = c[2]; g3 = c[3]; }

                const float4 bs = d_bsum4[h];
                const float4 wA = d_wihp[2 * h];
                const float4 wB = d_wihp[2 * h + 1];
                g0 += bs.x + vv.x * wA.x + vv.y * wA.y;
                g1 += bs.y + vv.x * wA.z + vv.y * wA.w;
                g2 += bs.z + vv.x * wB.x + vv.y * wB.y;
                g3 += bs.w + vv.x * wB.z + vv.y * wB.w;

                const float ig = 1.f / (1.f + __expf(-g0));
                const float fg = 1.f / (1.f + __expf(-g1));
                const float gg = tanhf(g2);
                const float og = 1.f / (1.f + __expf(-g3));

                const int idx = myrow * NHD + h;
                const float cn = fg * cxp[idx] + ig * gg;
                cxp[idx] = cn;
                hxp[idx] = __float2half(og * tanhf(cn));
            }
        }
        __threadfence();
        __syncthreads();
        if (tid == 0) atomicAdd(&d_scnt[L + 1][m0 >> 7], 1);
        return;
    }

    // R_G / R_ENCH: fp16 out (+relu for G); R_ENCC: fp32 out + bias
    {
        const int N = (role == R_G) ? NGD : NHD;
        __half* Ch = (role == R_G) ? &d_gbufh[(L - 1) & (RING - 1)][0]
                                   : &d_hxh[0][0];
#pragma unroll
        for (int ti = 0; ti < 4; ti++) {
            const int r0 = m0 + wm + ti * 16 + lg;
#pragma unroll
            for (int tj = 0; tj < 4; tj++) {
                const int col = n0 + wn + tj * 8 + 2 * l4;
                float* c = acc[ti][tj];
                float b0 = 0.f, b1 = 0.f;
                if (role == R_ENCH) { b0 = d_encb1[col]; b1 = d_encb1[col + 1]; }
                if (role == R_ENCC) { b0 = d_encb2[col]; b1 = d_encb2[col + 1]; }
                float x0 = c[0] + b0, x1 = c[1] + b1;
                float x2 = c[2] + b0, x3 = c[3] + b1;
                if (role == R_G) {
                    x0 = fmaxf(x0, 0.f); x1 = fmaxf(x1, 0.f);
                    x2 = fmaxf(x2, 0.f); x3 = fmaxf(x3, 0.f);
                }
                if (role == R_ENCC) {
                    *(float2*)(d_cx + (size_t)r0 * N + col)       = make_float2(x0, x1);
                    *(float2*)(d_cx + (size_t)(r0 + 8) * N + col) = make_float2(x2, x3);
                } else {
                    *(__half2*)(Ch + (size_t)r0 * N + col)       = __floats2half2_rn(x0, x1);
                    *(__half2*)(Ch + (size_t)(r0 + 8) * N + col) = __floats2half2_rn(x2, x3);
                }
            }
        }
        __threadfence();
        __syncthreads();
        if (tid == 0) {
            if (role == R_G)  atomicAdd(&d_gcnt[L - 1][m0 >> 7], 1);
            else              atomicAdd(&d_scnt[0][m0 >> 7], 4);   // ENCH/ENCC
        }
    }
}

// ---------------------------------------------------------------------------
// ONE fused prep kernel (conversions + permute + bias packs + counter zeroing)
// Segments are in float4 / work-item units, dispatched by global index.
// ---------------------------------------------------------------------------
#define SEG_P0   131072                         // BATCH*NPD/4
#define SEG_E1   65536                          // NHD*NPD/4
#define SEG_E2   65536
#define SEG_GW   524288                         // NGD*NHD/4
#define SEG_DC   524288                         // NPD*NGD/4
#define SEG_WH   262144                         // 4*NHD*NHD/4 (permute items)
#define SEG_HB   512
#define SEG_ZC   912                            // 64*8 + 50*8
#define OFF_E1   (SEG_P0)
#define OFF_E2   (OFF_E1 + SEG_E1)
#define OFF_GW   (OFF_E2 + SEG_E2)
#define OFF_DC   (OFF_GW + SEG_GW)
#define OFF_WH   (OFF_DC + SEG_DC)
#define OFF_HB   (OFF_WH + SEG_WH)
#define OFF_ZC   (OFF_HB + SEG_HB)
#define PREP_TOT (OFF_ZC + SEG_ZC)

__device__ __forceinline__ void cvt4(const float* s, __half2* d, int i)
{
    const float4 x = ((const float4*)s)[i];
    d[i * 2]     = __floats2half2_rn(x.x, x.y);
    d[i * 2 + 1] = __floats2half2_rn(x.z, x.w);
}

__global__ void prep_all(const float* __restrict__ p0,
                         const float* __restrict__ e1w, const float* __restrict__ e2w,
                         const float* __restrict__ gw,  const float* __restrict__ dw,
                         const float* __restrict__ whh, const float* __restrict__ wih,
                         const float* __restrict__ bi,  const float* __restrict__ bh,
                         const float* __restrict__ e1b, const float* __restrict__ e2b,
                         const float* __restrict__ db)
{
    const int gi = blockIdx.x * 256 + threadIdx.x;
    if (gi < OFF_E1) {
        cvt4(p0, (__half2*)d_p0h, gi);
    } else if (gi < OFF_E2) {
        cvt4(e1w, (__half2*)d_e1h, gi - OFF_E1);
    } else if (gi < OFF_GW) {
        cvt4(e2w, (__half2*)d_e2h, gi - OFF_E2);
    } else if (gi < OFF_DC) {
        cvt4(gw, (__half2*)d_gwh, gi - OFF_GW);
    } else if (gi < OFF_WH) {
        cvt4(dw, (__half2*)d_dech, gi - OFF_DC);
    } else if (gi < OFF_HB) {
        const int i = gi - OFF_WH;
        const int n = i >> 7;
        const int q = i & 127;
        const int src = ((n & 3) << 9) + (n >> 2);
        const float4 x = *(const float4*)(whh + (size_t)src * NHD + (q << 2));
        __half2* d = (__half2*)d_whhh;
        d[(size_t)n * (NHD / 2) + q * 2]     = __floats2half2_rn(x.x, x.y);
        d[(size_t)n * (NHD / 2) + q * 2 + 1] = __floats2half2_rn(x.z, x.w);
    } else if (gi < OFF_ZC) {
        const int h = gi - OFF_HB;
        d_bsum4[h] = make_float4(bi[h] + bh[h],
                                 bi[NHD + h] + bh[NHD + h],
                                 bi[2 * NHD + h] + bh[2 * NHD + h],
                                 bi[3 * NHD + h] + bh[3 * NHD + h]);
        d_wihp[2 * h] = make_float4(wih[h * 2], wih[h * 2 + 1],
                                    wih[(NHD + h) * 2], wih[(NHD + h) * 2 + 1]);
        d_wihp[2 * h + 1] = make_float4(wih[(2 * NHD + h) * 2], wih[(2 * NHD + h) * 2 + 1],
                                        wih[(3 * NHD + h) * 2], wih[(3 * NHD + h) * 2 + 1]);
        d_encb1[h] = e1b[h];
        d_encb2[h] = e2b[h];
        d_decb[h]  = db[h];
    } else if (gi < PREP_TOT) {
        const int i = gi - OFF_ZC;
        if (i < 512) (&d_scnt[0][0])[i] = 0;
        else         (&d_gcnt[0][0])[i - 512] = 0;
    }
}

// ---------------------------------------------------------------------------
static void launch_mega(int L, float* out, const float* vp, int grid, bool pdl)
{
    cudaLaunchConfig_t cfg = {};
    cfg.gridDim          = dim3(grid, 1, 1);
    cfg.blockDim         = dim3(256, 1, 1);
    cfg.dynamicSmemBytes = SMEM_DYN;
    cfg.stream           = 0;
    cudaLaunchAttribute attr[1];
    attr[0].id = cudaLaunchAttributeProgrammaticStreamSerialization;
    attr[0].val.programmaticStreamSerializationAllowed = 1;
    cfg.attrs    = attr;
    cfg.numAttrs = pdl ? 1 : 0;
    cudaLaunchKernelEx(&cfg, mega, L, out, vp);
}

extern "C" void kernel_launch(void* const* d_in, const int* in_sizes, int n_in,
                              void* d_out, int out_size)
{
    const float* v      = (const float*)d_in[0];
    const float* p0     = (const float*)d_in[1];
    const float* enc1_w = (const float*)d_in[2];
    const float* enc1_b = (const float*)d_in[3];
    const float* enc2_w = (const float*)d_in[4];
    const float* enc2_b = (const float*)d_in[5];
    const float* w_ih   = (const float*)d_in[6];
    const float* w_hh   = (const float*)d_in[7];
    const float* b_ih   = (const float*)d_in[8];
    const float* b_hh   = (const float*)d_in[9];
    const float* g_w    = (const float*)d_in[10];
    const float* dec_w  = (const float*)d_in[11];
    const float* dec_b  = (const float*)d_in[12];
    float* out = (float*)d_out;

    cudaFuncSetAttribute(mega, cudaFuncAttributeMaxDynamicSharedMemorySize,
                         SMEM_DYN);

    // launch 0: all prep in one kernel
    prep_all<<<(PREP_TOT + 255) / 256, 256>>>(
        p0, enc1_w, enc2_w, g_w, dec_w, w_hh, w_ih,
        b_ih, b_hh, enc1_b, enc2_b, dec_b);

    // launch 1: encoder (no PDL; must wait for prep)
    launch_mega(-1, out, v, 64, false);

    // launches 2..: step launches with PDL overlap (ncu -s 5 hits mega L=3)
    for (int L = 0; L <= T_STEPS + 1; L++)
        launch_mega(L, out, v, 416, true);
}

// round 14
// speedup vs baseline: 1.0763x; 1.0763x over previous
#include <cuda_runtime.h>
#include <cuda_fp16.h>
#include <math.h>
#include <stdint.h>

#define T_STEPS 50
#define BATCH   1024
#define NPD     512
#define NHD     512
#define NGD     4096
#define RING    16
#define HXB     8

#define RP        144u                    // row pitch bytes (72 halves) — 4r mod 32 banks
#define STAGE_B   (256u * RP)             // 36864 B : 256 rows x 128 B data (K=64)
#define NSTAGE    3
#define SMEM_DYN  (NSTAGE * STAGE_B)      // 110592 B  (2 CTAs/SM = 221 KB <= 228 KB)

// ---------------- device scratch (no cudaMalloc allowed) ----------------
__device__ __half d_hxh[HXB][BATCH * NHD];
__device__ float  d_cx[BATCH * NHD];
__device__ __half d_gbufh[RING][(size_t)BATCH * NGD];     // 128 MB ring
__device__ __half d_p0h[BATCH * NPD];
__device__ __half d_e1h[NHD * NPD];
__device__ __half d_e2h[NHD * NPD];
__device__ __half d_whhh[4 * NHD * NHD];                  // permuted [h*4+g][k]
__device__ __half d_gwh[(size_t)NGD * NHD];
__device__ __half d_dech[(size_t)NPD * NGD];
__device__ float4 d_bsum4[NHD];
__device__ float4 d_wihp[2 * NHD];
__device__ float  d_encb1[NHD];
__device__ float  d_encb2[NHD];
__device__ float  d_decb[NPD];

// dataflow counters (zeroed per replay)
__device__ int d_scnt[64][8];             // hx block ready (16/launch + 32 enc)
__device__ int d_gcnt[T_STEPS][8];        // g m-block ready: 32 n-tiles each

__device__ __forceinline__ uint32_t sm_u32(const void* p) {
    return (uint32_t)__cvta_generic_to_shared(p);
}

#define CP_ASYNC16(dst, src) \
    asm volatile("cp.async.cg.shared.global [%0], [%1], 16;\n" :: "r"(dst), "l"(src))
#define CP_COMMIT() asm volatile("cp.async.commit_group;\n" ::: "memory")
#define CP_WAIT0()  asm volatile("cp.async.wait_group 0;\n" ::: "memory")
#define CP_WAIT1()  asm volatile("cp.async.wait_group 1;\n" ::: "memory")

#define LDSM_X4(r0, r1, r2, r3, addr) \
    asm volatile("ldmatrix.sync.aligned.m8n8.x4.shared.b16 {%0,%1,%2,%3}, [%4];" \
                 : "=r"(r0), "=r"(r1), "=r"(r2), "=r"(r3) : "r"(addr))

__device__ __forceinline__ void mma_f16(float* c, uint32_t a0, uint32_t a1,
                                        uint32_t a2, uint32_t a3,
                                        uint32_t b0, uint32_t b1)
{
    asm volatile(
        "mma.sync.aligned.m16n8k16.row.col.f32.f16.f16.f32 "
        "{%0,%1,%2,%3}, {%4,%5,%6,%7}, {%8,%9}, {%0,%1,%2,%3};"
        : "+f"(c[0]), "+f"(c[1]), "+f"(c[2]), "+f"(c[3])
        : "r"(a0), "r"(a1), "r"(a2), "r"(a3), "r"(b0), "r"(b1));
}

__device__ __forceinline__ void spin_ge(volatile int* p, int target) {
    while (*p < target) __nanosleep(64);
}

// roles
#define R_GATES 0
#define R_G     1
#define R_DEC   2
#define R_ENCH  3
#define R_ENCC  4

// ---------------------------------------------------------------------------
// Mega kernel, one CTA per fp16 GEMM tile, K processed in 64-wide chunks
// (4 ks-groups between barriers). Step launch L in [0, 52):
//   bx [0,128)   : gates(t=L)    128x128x512, fused LSTM cell  [valid L<50]
//   bx [128,160) : decode(td=L-2) 128x128x4096, single write   [valid td<50]
//   bx [160,416) : g(t=L-1)      128x128x512, relu -> ring     [valid 1<=L<=50]
// L=-1: encoder (64 CTAs). PDL trigger at entry; true deps via counters.
// ---------------------------------------------------------------------------
__global__ void __launch_bounds__(256, 2)
mega(int L, float* __restrict__ out, const float* __restrict__ vp)
{
    asm volatile("griddepcontrol.launch_dependents;" ::: "memory");

    extern __shared__ __align__(16) char smraw[];
    const uint32_t smb = sm_u32(smraw);

    const int tid  = threadIdx.x;
    const int lane = tid & 31;
    const int wid  = tid >> 5;
    const int lg   = lane >> 2;
    const int l4   = lane & 3;
    const int wm   = (wid >> 2) * 64;
    const int wn   = (wid & 3) * 32;
    const int bx   = blockIdx.x;

    int role, m0, n0, td = 0, lda, KT = 8;      // KT in 64-wide chunks
    const __half *Ab, *Wb;

    if (L < 0) {
        role = (bx < 32) ? R_ENCH : R_ENCC;
        const int s = bx & 31;
        m0 = (s >> 2) << 7; n0 = (s & 3) << 7;
        Ab = d_p0h + (size_t)m0 * NPD;
        Wb = ((role == R_ENCH) ? d_e1h : d_e2h) + (size_t)n0 * NPD;
        lda = 512;
    } else if (bx < 128) {
        if (L >= T_STEPS) return;
        role = R_GATES;
        n0 = (bx & 15) << 7; m0 = (bx >> 4) << 7;
        Ab = &d_hxh[L % HXB][0] + (size_t)m0 * NHD;
        Wb = d_whhh + (size_t)n0 * NHD;
        lda = 512;
    } else if (bx < 160) {
        td = L - 2;
        if (td < 0 || td >= T_STEPS) return;
        role = R_DEC;
        const int s = bx - 128;           // 0..31
        m0 = (s >> 2) << 7; n0 = (s & 3) << 7;
        Ab = &d_gbufh[td & (RING - 1)][0] + (size_t)m0 * NGD;
        Wb = d_dech + (size_t)n0 * NGD;
        lda = NGD;
        KT = 64;
    } else {
        if (L < 1 || L > T_STEPS) return;
        role = R_G;
        const int s = bx - 160;
        n0 = (s & 31) << 7; m0 = (s >> 5) << 7;
        Ab = &d_hxh[L % HXB][0] + (size_t)m0 * NHD;
        Wb = d_gwh + (size_t)n0 * NHD;
        lda = 512;
    }

    // ---- wait for true data dependencies (producers in earlier launches) ----
    if (tid == 0) {
        if (role == R_GATES || role == R_G)
            spin_ge(&d_scnt[L][m0 >> 7], (L == 0) ? 32 : 16);
        else if (role == R_DEC)
            spin_ge(&d_gcnt[td][m0 >> 7], 32);
        __threadfence();
    }
    __syncthreads();

    float acc[4][4][4];
#pragma unroll
    for (int i = 0; i < 4; i++)
#pragma unroll
        for (int j = 0; j < 4; j++)
#pragma unroll
            for (int e = 0; e < 4; e++) acc[i][j][e] = 0.f;

    // stage loader: 256 rows x 128 B (K=64 halves), 8 cp.async per thread
    auto load_stage = [&](int kt, int stage) {
        const uint32_t sb = smb + stage * STAGE_B;
#pragma unroll
        for (int it = 0; it < 8; it++) {
            const int i    = tid + it * 256;
            const int row  = i >> 3;
            const int quad = i & 7;
            const __half* src =
                ((row < 128) ? Ab + (size_t)row * lda
                             : Wb + (size_t)(row - 128) * lda)
                + (kt << 6) + (quad << 3);
            CP_ASYNC16(sb + row * RP + (quad << 4), src);
        }
        CP_COMMIT();
    };

    // ldmatrix lane base addresses (stage 0, ks 0; add stage/ks offsets per use)
    uint32_t aAdr[4], bAdr[2];
#pragma unroll
    for (int ti = 0; ti < 4; ti++)
        aAdr[ti] = smb + (wm + ti * 16 + (lane & 15)) * RP + ((lane >> 4) << 4);
#pragma unroll
    for (int p = 0; p < 2; p++)
        bAdr[p] = smb + (128 + wn + p * 16 + ((lane >> 4) << 3) + (lane & 7)) * RP
                + (((lane >> 3) & 1) << 4);

    load_stage(0, 0);
    load_stage(1, 1);
    int issued = 2, cs = 0, ls = 2;

#pragma unroll 1
    for (int kt = 0; kt < KT; kt++) {
        if (issued - kt - 1 >= 1) { CP_WAIT1(); } else { CP_WAIT0(); }
        __syncthreads();
        if (issued < KT) {
            load_stage(issued, ls);
            issued++;
            ls = (ls == 2) ? 0 : ls + 1;
        }

        const uint32_t so = cs * STAGE_B;
#pragma unroll
        for (int ks = 0; ks < 4; ks++) {
            const uint32_t ko = so + ks * 32;
            uint32_t af[4][4], bf[2][4];
#pragma unroll
            for (int p = 0; p < 2; p++)
                LDSM_X4(bf[p][0], bf[p][1], bf[p][2], bf[p][3], bAdr[p] + ko);
#pragma unroll
            for (int ti = 0; ti < 4; ti++)
                LDSM_X4(af[ti][0], af[ti][1], af[ti][2], af[ti][3], aAdr[ti] + ko);
#pragma unroll
            for (int ti = 0; ti < 4; ti++)
#pragma unroll
                for (int tj = 0; tj < 4; tj++)
                    mma_f16(acc[ti][tj],
                            af[ti][0], af[ti][1], af[ti][2], af[ti][3],
                            bf[tj >> 1][(tj & 1) * 2],
                            bf[tj >> 1][(tj & 1) * 2 + 1]);
        }
        cs = (cs == 2) ? 0 : cs + 1;
    }

    // ---------------- epilogues ----------------
    if (role == R_DEC) {
        float* ob = out + (size_t)td * BATCH * NPD;
#pragma unroll
        for (int ti = 0; ti < 4; ti++) {
            const int r0 = m0 + wm + ti * 16 + lg;
#pragma unroll
            for (int tj = 0; tj < 4; tj++) {
                const int col = n0 + wn + tj * 8 + 2 * l4;
                float* c = acc[ti][tj];
                const float b0 = d_decb[col], b1 = d_decb[col + 1];
                *(float2*)(ob + (size_t)r0 * NPD + col) =
                    make_float2(c[0] + b0, c[1] + b1);
                *(float2*)(ob + (size_t)(r0 + 8) * NPD + col) =
                    make_float2(c[2] + b0, c[3] + b1);
            }
        }
        return;
    }

    if (role == R_GATES) {
        float*  cxp = d_cx;
        __half* hxp = &d_hxh[(L + 1) % HXB][0];
        const int hbase = (n0 >> 2) + (wn >> 2);
#pragma unroll
        for (int ti = 0; ti < 4; ti++) {
            const int myrow = m0 + wm + ti * 16 + lg + ((l4 & 1) << 3);
            const float2 vv = *(const float2*)(vp + ((size_t)L * BATCH + myrow) * 2);
#pragma unroll
            for (int tj = 0; tj < 4; tj++) {
                const int h = hbase + tj * 2 + (l4 >> 1);
                float* c = acc[ti][tj];
                float2 send = (l4 & 1) ? make_float2(c[0], c[1])
                                       : make_float2(c[2], c[3]);
                float2 recv;
                recv.x = __shfl_xor_sync(0xffffffffu, send.x, 1);
                recv.y = __shfl_xor_sync(0xffffffffu, send.y, 1);
                float g0, g1, g2, g3;
                if (!(l4 & 1)) { g0 = c[0]; g1 = c[1]; g2 = recv.x; g3 = recv.y; }
                else           { g0 = recv.x; g1 = recv.y; g2 = c[2]; g3 = c[3]; }

                const float4 bs = d_bsum4[h];
                const float4 wA = d_wihp[2 * h];
                const float4 wB = d_wihp[2 * h + 1];
                g0 += bs.x + vv.x * wA.x + vv.y * wA.y;
                g1 += bs.y + vv.x * wA.z + vv.y * wA.w;
                g2 += bs.z + vv.x * wB.x + vv.y * wB.y;
                g3 += bs.w + vv.x * wB.z + vv.y * wB.w;

                const float ig = 1.f / (1.f + __expf(-g0));
                const float fg = 1.f / (1.f + __expf(-g1));
                const float gg = tanhf(g2);
                const float og = 1.f / (1.f + __expf(-g3));

                const int idx = myrow * NHD + h;
                const float cn = fg * cxp[idx] + ig * gg;
                cxp[idx] = cn;
                hxp[idx] = __float2half(og * tanhf(cn));
            }
        }
        __threadfence();
        __syncthreads();
        if (tid == 0) atomicAdd(&d_scnt[L + 1][m0 >> 7], 1);
        return;
    }

    // R_G / R_ENCH: fp16 out (+relu for G); R_ENCC: fp32 out + bias
    {
        const int N = (role == R_G) ? NGD : NHD;
        __half* Ch = (role == R_G) ? &d_gbufh[(L - 1) & (RING - 1)][0]
                                   : &d_hxh[0][0];
#pragma unroll
        for (int ti = 0; ti < 4; ti++) {
            const int r0 = m0 + wm + ti * 16 + lg;
#pragma unroll
            for (int tj = 0; tj < 4; tj++) {
                const int col = n0 + wn + tj * 8 + 2 * l4;
                float* c = acc[ti][tj];
                float b0 = 0.f, b1 = 0.f;
                if (role == R_ENCH) { b0 = d_encb1[col]; b1 = d_encb1[col + 1]; }
                if (role == R_ENCC) { b0 = d_encb2[col]; b1 = d_encb2[col + 1]; }
                float x0 = c[0] + b0, x1 = c[1] + b1;
                float x2 = c[2] + b0, x3 = c[3] + b1;
                if (role == R_G) {
                    x0 = fmaxf(x0, 0.f); x1 = fmaxf(x1, 0.f);
                    x2 = fmaxf(x2, 0.f); x3 = fmaxf(x3, 0.f);
                }
                if (role == R_ENCC) {
                    *(float2*)(d_cx + (size_t)r0 * N + col)       = make_float2(x0, x1);
                    *(float2*)(d_cx + (size_t)(r0 + 8) * N + col) = make_float2(x2, x3);
                } else {
                    *(__half2*)(Ch + (size_t)r0 * N + col)       = __floats2half2_rn(x0, x1);
                    *(__half2*)(Ch + (size_t)(r0 + 8) * N + col) = __floats2half2_rn(x2, x3);
                }
            }
        }
        __threadfence();
        __syncthreads();
        if (tid == 0) {
            if (role == R_G)  atomicAdd(&d_gcnt[L - 1][m0 >> 7], 1);
            else              atomicAdd(&d_scnt[0][m0 >> 7], 4);   // ENCH/ENCC
        }
    }
}

// ---------------------------------------------------------------------------
// ONE fused prep kernel (conversions + permute + bias packs + counter zeroing)
// ---------------------------------------------------------------------------
#define SEG_P0   131072
#define SEG_E1   65536
#define SEG_E2   65536
#define SEG_GW   524288
#define SEG_DC   524288
#define SEG_WH   262144
#define SEG_HB   512
#define SEG_ZC   912
#define OFF_E1   (SEG_P0)
#define OFF_E2   (OFF_E1 + SEG_E1)
#define OFF_GW   (OFF_E2 + SEG_E2)
#define OFF_DC   (OFF_GW + SEG_GW)
#define OFF_WH   (OFF_DC + SEG_DC)
#define OFF_HB   (OFF_WH + SEG_WH)
#define OFF_ZC   (OFF_HB + SEG_HB)
#define PREP_TOT (OFF_ZC + SEG_ZC)

__device__ __forceinline__ void cvt4(const float* s, __half2* d, int i)
{
    const float4 x = ((const float4*)s)[i];
    d[i * 2]     = __floats2half2_rn(x.x, x.y);
    d[i * 2 + 1] = __floats2half2_rn(x.z, x.w);
}

__global__ void prep_all(const float* __restrict__ p0,
                         const float* __restrict__ e1w, const float* __restrict__ e2w,
                         const float* __restrict__ gw,  const float* __restrict__ dw,
                         const float* __restrict__ whh, const float* __restrict__ wih,
                         const float* __restrict__ bi,  const float* __restrict__ bh,
                         const float* __restrict__ e1b, const float* __restrict__ e2b,
                         const float* __restrict__ db)
{
    const int gi = blockIdx.x * 256 + threadIdx.x;
    if (gi < OFF_E1) {
        cvt4(p0, (__half2*)d_p0h, gi);
    } else if (gi < OFF_E2) {
        cvt4(e1w, (__half2*)d_e1h, gi - OFF_E1);
    } else if (gi < OFF_GW) {
        cvt4(e2w, (__half2*)d_e2h, gi - OFF_E2);
    } else if (gi < OFF_DC) {
        cvt4(gw, (__half2*)d_gwh, gi - OFF_GW);
    } else if (gi < OFF_WH) {
        cvt4(dw, (__half2*)d_dech, gi - OFF_DC);
    } else if (gi < OFF_HB) {
        const int i = gi - OFF_WH;
        const int n = i >> 7;
        const int q = i & 127;
        const int src = ((n & 3) << 9) + (n >> 2);
        const float4 x = *(const float4*)(whh + (size_t)src * NHD + (q << 2));
        __half2* d = (__half2*)d_whhh;
        d[(size_t)n * (NHD / 2) + q * 2]     = __floats2half2_rn(x.x, x.y);
        d[(size_t)n * (NHD / 2) + q * 2 + 1] = __floats2half2_rn(x.z, x.w);
    } else if (gi < OFF_ZC) {
        const int h = gi - OFF_HB;
        d_bsum4[h] = make_float4(bi[h] + bh[h],
                                 bi[NHD + h] + bh[NHD + h],
                                 bi[2 * NHD + h] + bh[2 * NHD + h],
                                 bi[3 * NHD + h] + bh[3 * NHD + h]);
        d_wihp[2 * h] = make_float4(wih[h * 2], wih[h * 2 + 1],
                                    wih[(NHD + h) * 2], wih[(NHD + h) * 2 + 1]);
        d_wihp[2 * h + 1] = make_float4(wih[(2 * NHD + h) * 2], wih[(2 * NHD + h) * 2 + 1],
                                        wih[(3 * NHD + h) * 2], wih[(3 * NHD + h) * 2 + 1]);
        d_encb1[h] = e1b[h];
        d_encb2[h] = e2b[h];
        d_decb[h]  = db[h];
    } else if (gi < PREP_TOT) {
        const int i = gi - OFF_ZC;
        if (i < 512) (&d_scnt[0][0])[i] = 0;
        else         (&d_gcnt[0][0])[i - 512] = 0;
    }
}

// ---------------------------------------------------------------------------
static void launch_mega(int L, float* out, const float* vp, int grid, bool pdl)
{
    cudaLaunchConfig_t cfg = {};
    cfg.gridDim          = dim3(grid, 1, 1);
    cfg.blockDim         = dim3(256, 1, 1);
    cfg.dynamicSmemBytes = SMEM_DYN;
    cfg.stream           = 0;
    cudaLaunchAttribute attr[1];
    attr[0].id = cudaLaunchAttributeProgrammaticStreamSerialization;
    attr[0].val.programmaticStreamSerializationAllowed = 1;
    cfg.attrs    = attr;
    cfg.numAttrs = pdl ? 1 : 0;
    cudaLaunchKernelEx(&cfg, mega, L, out, vp);
}

extern "C" void kernel_launch(void* const* d_in, const int* in_sizes, int n_in,
                              void* d_out, int out_size)
{
    const float* v      = (const float*)d_in[0];
    const float* p0     = (const float*)d_in[1];
    const float* enc1_w = (const float*)d_in[2];
    const float* enc1_b = (const float*)d_in[3];
    const float* enc2_w = (const float*)d_in[4];
    const float* enc2_b = (const float*)d_in[5];
    const float* w_ih   = (const float*)d_in[6];
    const float* w_hh   = (const float*)d_in[7];
    const float* b_ih   = (const float*)d_in[8];
    const float* b_hh   = (const float*)d_in[9];
    const float* g_w    = (const float*)d_in[10];
    const float* dec_w  = (const float*)d_in[11];
    const float* dec_b  = (const float*)d_in[12];
    float* out = (float*)d_out;

    cudaFuncSetAttribute(mega, cudaFuncAttributeMaxDynamicSharedMemorySize,
                         SMEM_DYN);

    // launch 0: all prep in one kernel
    prep_all<<<(PREP_TOT + 255) / 256, 256>>>(
        p0, enc1_w, enc2_w, g_w, dec_w, w_hh, w_ih,
        b_ih, b_hh, enc1_b, enc2_b, dec_b);

    // launch 1: encoder (no PDL; must wait for prep)
    launch_mega(-1, out, v, 64, false);

    // launches 2..: step launches with PDL overlap (ncu -s 5 hits mega L=3)
    for (int L = 0; L <= T_STEPS + 1; L++)
        launch_mega(L, out, v, 416, true);
}